// round 1
// baseline (speedup 1.0000x reference)
#include <cuda_runtime.h>
#include <math.h>

#define NTOK 8192

// ---------------- scratch (static device buffers; no allocation) ----------------
__device__ float g_A[NTOK * 128];
__device__ float g_B[NTOK * 128];
__device__ float g_Qb[NTOK * 128];
__device__ float g_Kb[NTOK * 128];   // row-major (local layer) OR transposed [128][NTOK] (global layers)
__device__ float g_Vb[NTOK * 128];
__device__ float g_Rb[NTOK * 128];
__device__ float g_H[NTOK * 256];

typedef unsigned long long u64;

// ---------------- packed f32x2 helpers (Blackwell FMA2 pipe) ----------------
__device__ __forceinline__ u64 dup2(float x) {
    u64 r; asm("mov.b64 %0, {%1, %1};" : "=l"(r) : "f"(x)); return r;
}
__device__ __forceinline__ void fma2(u64 &d, u64 a, u64 b) {
    asm("fma.rn.f32x2 %0, %1, %2, %0;" : "+l"(d) : "l"(a), "l"(b));
}
__device__ __forceinline__ void mul2(u64 &d, u64 a) {
    asm("mul.rn.f32x2 %0, %0, %1;" : "+l"(d) : "l"(a));
}
__device__ __forceinline__ float2 unp2(u64 v) {
    float2 f; asm("mov.b64 {%0, %1}, %2;" : "=f"(f.x), "=f"(f.y) : "l"(v)); return f;
}
__device__ __forceinline__ float gelu_f(float x) {
    return 0.5f * x * (1.0f + erff(x * 0.7071067811865476f));
}

// ---------------- fc0: [N,3] @ [3,128] + b ----------------
__global__ void __launch_bounds__(256) fc0_kernel(
    const float* __restrict__ x, const float* __restrict__ w,
    const float* __restrict__ b, float* __restrict__ out)
{
    int idx = blockIdx.x * 256 + threadIdx.x;          // N*128 threads
    int n = idx >> 7, c = idx & 127;
    float x0 = x[n * 3 + 0], x1 = x[n * 3 + 1], x2 = x[n * 3 + 2];
    out[idx] = fmaf(x0, w[c], fmaf(x1, w[128 + c], fmaf(x2, w[256 + c], b[c])));
}

// ---------------- generic GEMM: C = act(X[N,128] @ W[128,M] + b) ----------------
// TRANS=1 writes C transposed as [M][NTOK] (used to pre-transpose K for flash attn).
template<int ACT, int TRANS>
__global__ void __launch_bounds__(256) gemm128_kernel(
    const float* __restrict__ X, const float* __restrict__ W,
    const float* __restrict__ bias, float* __restrict__ C, int M)
{
    __shared__ float Xt[32][64];     // transposed X chunk: Xt[k][m]
    __shared__ float Ws[32][128];    // W chunk
    int tid = threadIdx.x;
    int n0 = blockIdx.x * 64;
    int cb = blockIdx.y * 128;
    int rg = tid >> 4, cg = tid & 15;      // 4-row x 8-col microtile

    u64 acc[4][4];
#pragma unroll
    for (int r = 0; r < 4; r++)
#pragma unroll
        for (int j = 0; j < 4; j++) acc[r][j] = 0ULL;

    for (int kc = 0; kc < 128; kc += 32) {
        __syncthreads();
        {
            int m = tid & 63, kk = (tid >> 6) << 2;
#pragma unroll
            for (int rep = 0; rep < 2; rep++) {
                float4 v = *(const float4*)&X[(n0 + m) * 128 + kc + kk];
                Xt[kk + 0][m] = v.x; Xt[kk + 1][m] = v.y;
                Xt[kk + 2][m] = v.z; Xt[kk + 3][m] = v.w;
                kk += 16;
            }
        }
        {
            int c4 = (tid & 31) << 2, k = tid >> 5;
#pragma unroll
            for (int rep = 0; rep < 4; rep++) {
                *(float4*)&Ws[k][c4] = *(const float4*)&W[(kc + k) * M + cb + c4];
                k += 8;
            }
        }
        __syncthreads();
#pragma unroll 8
        for (int k = 0; k < 32; k++) {
            float4 xv = *(const float4*)&Xt[k][rg << 2];
            const float* wrow = &Ws[k][cg << 3];
            ulonglong2 w0 = *(const ulonglong2*)(wrow);
            ulonglong2 w1 = *(const ulonglong2*)(wrow + 4);
            u64 x0 = dup2(xv.x), x1 = dup2(xv.y), x2 = dup2(xv.z), x3 = dup2(xv.w);
            fma2(acc[0][0], x0, w0.x); fma2(acc[0][1], x0, w0.y);
            fma2(acc[0][2], x0, w1.x); fma2(acc[0][3], x0, w1.y);
            fma2(acc[1][0], x1, w0.x); fma2(acc[1][1], x1, w0.y);
            fma2(acc[1][2], x1, w1.x); fma2(acc[1][3], x1, w1.y);
            fma2(acc[2][0], x2, w0.x); fma2(acc[2][1], x2, w0.y);
            fma2(acc[2][2], x2, w1.x); fma2(acc[2][3], x2, w1.y);
            fma2(acc[3][0], x3, w0.x); fma2(acc[3][1], x3, w0.y);
            fma2(acc[3][2], x3, w1.x); fma2(acc[3][3], x3, w1.y);
        }
    }

    float o[4][8];
#pragma unroll
    for (int r = 0; r < 4; r++)
#pragma unroll
        for (int j = 0; j < 4; j++) {
            float2 f = unp2(acc[r][j]);
            o[r][2 * j] = f.x; o[r][2 * j + 1] = f.y;
        }
#pragma unroll
    for (int r = 0; r < 4; r++)
#pragma unroll
        for (int j = 0; j < 8; j++) {
            float v = o[r][j] + bias[cb + (cg << 3) + j];
            if (ACT) v = gelu_f(v);
            o[r][j] = v;
        }
    if (!TRANS) {
#pragma unroll
        for (int r = 0; r < 4; r++) {
            int row = n0 + (rg << 2) + r;
            *(float4*)&C[row * M + cb + (cg << 3)]     = make_float4(o[r][0], o[r][1], o[r][2], o[r][3]);
            *(float4*)&C[row * M + cb + (cg << 3) + 4] = make_float4(o[r][4], o[r][5], o[r][6], o[r][7]);
        }
    } else {
#pragma unroll
        for (int j = 0; j < 8; j++) {
            int c = cb + (cg << 3) + j;
            *(float4*)&C[c * NTOK + n0 + (rg << 2)] = make_float4(o[0][j], o[1][j], o[2][j], o[3][j]);
        }
    }
}

// ---------------- flash global attention ----------------
// out = maybe_gelu( softmax(Q Ktr / sqrt(128)) / N @ V + R )
// Q: [N,128] row-major, Ktr: [128][N] (pre-transposed), V: [N,128], R: [N,128]
#define FLASH_SMEM 114688   // (128*64 + 128*64 + 64*128 + 64*64) * 4 bytes

__global__ void __launch_bounds__(256) flash_kernel(
    const float* __restrict__ Q, const float* __restrict__ Ktr,
    const float* __restrict__ V, const float* __restrict__ R,
    float* __restrict__ Out, int applyGelu)
{
    extern __shared__ float smem[];
    float* Qt = smem;                 // [128][64] transposed, pre-scaled
    float* Kt = Qt + 128 * 64;        // [128][64]
    float* Vs = Kt + 128 * 64;        // [64][128]
    float* Ps = Vs + 64 * 128;        // [64][64] row-major P tile

    int tid = threadIdx.x;
    int rg = tid >> 4, cg = tid & 15;
    int m0 = blockIdx.x * 64;
    const float SCALE = 0.08838834764831843f;   // 1/sqrt(128)

    // load Q tile transposed (once)
    {
        int m = tid & 63, kq = (tid >> 6) << 2;
#pragma unroll
        for (int rep = 0; rep < 8; rep++) {
            float4 v = *(const float4*)&Q[(m0 + m) * 128 + kq];
            Qt[(kq + 0) * 64 + m] = v.x * SCALE;
            Qt[(kq + 1) * 64 + m] = v.y * SCALE;
            Qt[(kq + 2) * 64 + m] = v.z * SCALE;
            Qt[(kq + 3) * 64 + m] = v.w * SCALE;
            kq += 16;
        }
    }

    u64 oacc[4][4];                 // rows r, col-pairs j -> cols cg*8 + 2j,2j+1
#pragma unroll
    for (int r = 0; r < 4; r++)
#pragma unroll
        for (int j = 0; j < 4; j++) oacc[r][j] = 0ULL;
    float mrow[4] = {-1e30f, -1e30f, -1e30f, -1e30f};
    float lrow[4] = {0.f, 0.f, 0.f, 0.f};

    for (int t = 0; t < 128; t++) {
        __syncthreads();   // previous O-GEMM done reading Kt/Vs/Ps
        {   // K tile from pre-transposed global: coalesced
            int n4 = (tid & 15) << 2, k = tid >> 4;
#pragma unroll
            for (int rep = 0; rep < 8; rep++) {
                *(float4*)&Kt[k * 64 + n4] = *(const float4*)&Ktr[k * NTOK + t * 64 + n4];
                k += 16;
            }
        }
        {   // V tile row-major: coalesced copy
            int c4 = (tid & 31) << 2, n = tid >> 5;
#pragma unroll
            for (int rep = 0; rep < 8; rep++) {
                *(float4*)&Vs[n * 128 + c4] = *(const float4*)&V[(t * 64 + n) * 128 + c4];
                n += 8;
            }
        }
        __syncthreads();

        // --- S = Qt^T Kt, thread tile 4 rows x 4 cols ---
        u64 sacc[4][2];
#pragma unroll
        for (int r = 0; r < 4; r++) { sacc[r][0] = 0ULL; sacc[r][1] = 0ULL; }
#pragma unroll 16
        for (int k = 0; k < 128; k++) {
            float4 qv = *(const float4*)&Qt[k * 64 + (rg << 2)];
            ulonglong2 kv = *(const ulonglong2*)&Kt[k * 64 + (cg << 2)];
            u64 q0 = dup2(qv.x), q1 = dup2(qv.y), q2 = dup2(qv.z), q3 = dup2(qv.w);
            fma2(sacc[0][0], q0, kv.x); fma2(sacc[0][1], q0, kv.y);
            fma2(sacc[1][0], q1, kv.x); fma2(sacc[1][1], q1, kv.y);
            fma2(sacc[2][0], q2, kv.x); fma2(sacc[2][1], q2, kv.y);
            fma2(sacc[3][0], q3, kv.x); fma2(sacc[3][1], q3, kv.y);
        }
        float s[4][4];
#pragma unroll
        for (int r = 0; r < 4; r++) {
            float2 a = unp2(sacc[r][0]); float2 b = unp2(sacc[r][1]);
            s[r][0] = a.x; s[r][1] = a.y; s[r][2] = b.x; s[r][3] = b.y;
        }

        // --- online softmax (row groups = 16 threads sharing rg, xor width 16) ---
#pragma unroll
        for (int r = 0; r < 4; r++) {
            float tmax = fmaxf(fmaxf(s[r][0], s[r][1]), fmaxf(s[r][2], s[r][3]));
#pragma unroll
            for (int o = 8; o; o >>= 1) tmax = fmaxf(tmax, __shfl_xor_sync(0xffffffffu, tmax, o));
            float mn = fmaxf(mrow[r], tmax);
            float f = __expf(mrow[r] - mn);
            mrow[r] = mn;
            float ps = 0.f;
#pragma unroll
            for (int c = 0; c < 4; c++) { s[r][c] = __expf(s[r][c] - mn); ps += s[r][c]; }
#pragma unroll
            for (int o = 8; o; o >>= 1) ps += __shfl_xor_sync(0xffffffffu, ps, o);
            lrow[r] = lrow[r] * f + ps;
            u64 fd = dup2(f);
            mul2(oacc[r][0], fd); mul2(oacc[r][1], fd); mul2(oacc[r][2], fd); mul2(oacc[r][3], fd);
        }

        // --- write P tile row-major (float4, conflict-free) ---
#pragma unroll
        for (int r = 0; r < 4; r++)
            *(float4*)&Ps[((rg << 2) + r) * 64 + (cg << 2)] =
                make_float4(s[r][0], s[r][1], s[r][2], s[r][3]);
        __syncthreads();

        // --- O += P @ V, thread tile 4 rows x 8 cols ---
#pragma unroll 8
        for (int n = 0; n < 64; n++) {
            u64 p0 = dup2(Ps[((rg << 2) + 0) * 64 + n]);
            u64 p1 = dup2(Ps[((rg << 2) + 1) * 64 + n]);
            u64 p2 = dup2(Ps[((rg << 2) + 2) * 64 + n]);
            u64 p3 = dup2(Ps[((rg << 2) + 3) * 64 + n]);
            const float* vrow = &Vs[n * 128 + (cg << 3)];
            ulonglong2 v0 = *(const ulonglong2*)(vrow);
            ulonglong2 v1 = *(const ulonglong2*)(vrow + 4);
            fma2(oacc[0][0], p0, v0.x); fma2(oacc[0][1], p0, v0.y);
            fma2(oacc[0][2], p0, v1.x); fma2(oacc[0][3], p0, v1.y);
            fma2(oacc[1][0], p1, v0.x); fma2(oacc[1][1], p1, v0.y);
            fma2(oacc[1][2], p1, v1.x); fma2(oacc[1][3], p1, v1.y);
            fma2(oacc[2][0], p2, v0.x); fma2(oacc[2][1], p2, v0.y);
            fma2(oacc[2][2], p2, v1.x); fma2(oacc[2][3], p2, v1.y);
            fma2(oacc[3][0], p3, v0.x); fma2(oacc[3][1], p3, v0.y);
            fma2(oacc[3][2], p3, v1.x); fma2(oacc[3][3], p3, v1.y);
        }
    }

    // --- epilogue: out = act(O/(l*N) + R) ---
#pragma unroll
    for (int r = 0; r < 4; r++) {
        int row = m0 + (rg << 2) + r;
        float inv = 1.0f / (lrow[r] * 8192.0f);
        float o[8];
#pragma unroll
        for (int j = 0; j < 4; j++) {
            float2 f = unp2(oacc[r][j]);
            o[2 * j] = f.x; o[2 * j + 1] = f.y;
        }
#pragma unroll
        for (int j = 0; j < 8; j++) {
            float v = o[j] * inv + R[row * 128 + (cg << 3) + j];
            if (applyGelu) v = gelu_f(v);
            o[j] = v;
        }
        *(float4*)&Out[row * 128 + (cg << 3)]     = make_float4(o[0], o[1], o[2], o[3]);
        *(float4*)&Out[row * 128 + (cg << 3) + 4] = make_float4(o[4], o[5], o[6], o[7]);
    }
}

// ---------------- local attention (K=32 neighbors, 8 heads x 16 dims) ----------------
__global__ void __launch_bounds__(256) local_attn_kernel(
    const float* __restrict__ Q, const float* __restrict__ K,
    const float* __restrict__ V, const int* __restrict__ nbr,
    const float* __restrict__ R, float* __restrict__ Out)
{
    __shared__ float qs[8][128];
    __shared__ float ps[8][8][32];
    __shared__ int   js[8][32];
    int w = threadIdx.x >> 5, lane = threadIdx.x & 31;
    int n = blockIdx.x * 8 + w;

    float4 qv = *(const float4*)&Q[n * 128 + lane * 4];
    *(float4*)&qs[w][lane * 4] = make_float4(qv.x * 0.25f, qv.y * 0.25f, qv.z * 0.25f, qv.w * 0.25f);
    int j = nbr[n * 32 + lane];
    js[w][lane] = j;
    __syncwarp();

    const float* krow = K + j * 128;
    float sc[8];
#pragma unroll
    for (int h = 0; h < 8; h++) {
        float4 a0 = *(const float4*)&krow[h * 16 + 0];
        float4 a1 = *(const float4*)&krow[h * 16 + 4];
        float4 a2 = *(const float4*)&krow[h * 16 + 8];
        float4 a3 = *(const float4*)&krow[h * 16 + 12];
        const float* q = &qs[w][h * 16];
        float sv = q[0] * a0.x + q[1] * a0.y + q[2] * a0.z + q[3] * a0.w
                 + q[4] * a1.x + q[5] * a1.y + q[6] * a1.z + q[7] * a1.w
                 + q[8] * a2.x + q[9] * a2.y + q[10] * a2.z + q[11] * a2.w
                 + q[12] * a3.x + q[13] * a3.y + q[14] * a3.z + q[15] * a3.w;
        sc[h] = sv;
    }
#pragma unroll
    for (int h = 0; h < 8; h++) {
        float mx = sc[h];
#pragma unroll
        for (int o = 16; o; o >>= 1) mx = fmaxf(mx, __shfl_xor_sync(0xffffffffu, mx, o));
        float p = __expf(sc[h] - mx);
        float su = p;
#pragma unroll
        for (int o = 16; o; o >>= 1) su += __shfl_xor_sync(0xffffffffu, su, o);
        ps[w][h][lane] = p / su;
    }
    __syncwarp();

    float acc[4] = {0.f, 0.f, 0.f, 0.f};
#pragma unroll 4
    for (int k = 0; k < 32; k++) {
        int jj = js[w][k];
        const float* vrow = V + jj * 128;
#pragma unroll
        for (int i = 0; i < 4; i++) {
            int c = lane + 32 * i;
            acc[i] += ps[w][c >> 4][k] * vrow[c];
        }
    }
#pragma unroll
    for (int i = 0; i < 4; i++) {
        int c = lane + 32 * i;
        float v = acc[i] + R[n * 128 + c];
        Out[n * 128 + c] = gelu_f(v);
    }
}

// ---------------- fc2: out[n] = H[n,:256] . w + b ----------------
__global__ void __launch_bounds__(256) fc2_kernel(
    const float* __restrict__ H, const float* __restrict__ w,
    const float* __restrict__ b, float* __restrict__ out)
{
    int n = (blockIdx.x * 256 + threadIdx.x) >> 5;
    int lane = threadIdx.x & 31;
    const float4* h4 = (const float4*)(H + n * 256);
    const float4* w4 = (const float4*)w;
    float acc = 0.f;
#pragma unroll
    for (int i = 0; i < 2; i++) {
        float4 hv = h4[lane + 32 * i];
        float4 wv = w4[lane + 32 * i];
        acc += hv.x * wv.x + hv.y * wv.y + hv.z * wv.z + hv.w * wv.w;
    }
#pragma unroll
    for (int o = 16; o; o >>= 1) acc += __shfl_xor_sync(0xffffffffu, acc, o);
    if (!lane) out[n] = acc + b[0];
}

// ---------------- host orchestration ----------------
extern "C" void kernel_launch(void* const* d_in, const int* in_sizes, int n_in,
                              void* d_out, int out_size)
{
    (void)in_sizes; (void)n_in; (void)out_size;
    const float* x     = (const float*)d_in[0];
    const float* fc0w  = (const float*)d_in[1];
    const float* fc0b  = (const float*)d_in[2];
    const float* fc1w  = (const float*)d_in[27];
    const float* fc1b  = (const float*)d_in[28];
    const float* fc2w  = (const float*)d_in[29];
    const float* fc2b  = (const float*)d_in[30];
    const int*   nbr   = (const int*)d_in[31];

    float *A, *B, *Qb, *Kb, *Vb, *Rb, *H;
    cudaGetSymbolAddress((void**)&A,  g_A);
    cudaGetSymbolAddress((void**)&B,  g_B);
    cudaGetSymbolAddress((void**)&Qb, g_Qb);
    cudaGetSymbolAddress((void**)&Kb, g_Kb);
    cudaGetSymbolAddress((void**)&Vb, g_Vb);
    cudaGetSymbolAddress((void**)&Rb, g_Rb);
    cudaGetSymbolAddress((void**)&H,  g_H);

    cudaFuncSetAttribute(flash_kernel, cudaFuncAttributeMaxDynamicSharedMemorySize, FLASH_SMEM);

    dim3 g64(NTOK / 64, 1);

    // fc0
    fc0_kernel<<<NTOK * 128 / 256, 256>>>(x, fc0w, fc0b, A);

    // ---- layer 0 (global, gelu) ----
    {
        const float* qw = (const float*)d_in[3];  const float* qbb = (const float*)d_in[4];
        const float* kw = (const float*)d_in[5];  const float* kbb = (const float*)d_in[6];
        const float* vw = (const float*)d_in[7];  const float* vbb = (const float*)d_in[8];
        const float* ww = (const float*)d_in[9];  const float* wbb = (const float*)d_in[10];
        gemm128_kernel<0, 0><<<g64, 256>>>(A, qw, qbb, Qb, 128);
        gemm128_kernel<0, 1><<<g64, 256>>>(A, kw, kbb, Kb, 128);   // K pre-transposed
        gemm128_kernel<0, 0><<<g64, 256>>>(A, vw, vbb, Vb, 128);
        gemm128_kernel<0, 0><<<g64, 256>>>(A, ww, wbb, Rb, 128);
        flash_kernel<<<NTOK / 64, 256, FLASH_SMEM>>>(Qb, Kb, Vb, Rb, B, 1);
    }

    // ---- layer 1 (local, gelu) ----
    {
        const float* qw = (const float*)d_in[11]; const float* qbb = (const float*)d_in[12];
        const float* kw = (const float*)d_in[13]; const float* kbb = (const float*)d_in[14];
        const float* vw = (const float*)d_in[15]; const float* vbb = (const float*)d_in[16];
        const float* ww = (const float*)d_in[17]; const float* wbb = (const float*)d_in[18];
        gemm128_kernel<0, 0><<<g64, 256>>>(B, qw, qbb, Qb, 128);
        gemm128_kernel<0, 0><<<g64, 256>>>(B, kw, kbb, Kb, 128);   // row-major for gather
        gemm128_kernel<0, 0><<<g64, 256>>>(B, vw, vbb, Vb, 128);
        gemm128_kernel<0, 0><<<g64, 256>>>(B, ww, wbb, Rb, 128);
        local_attn_kernel<<<NTOK / 8, 256>>>(Qb, Kb, Vb, nbr, Rb, A);
    }

    // ---- layer 2 (global, no activation) ----
    {
        const float* qw = (const float*)d_in[19]; const float* qbb = (const float*)d_in[20];
        const float* kw = (const float*)d_in[21]; const float* kbb = (const float*)d_in[22];
        const float* vw = (const float*)d_in[23]; const float* vbb = (const float*)d_in[24];
        const float* ww = (const float*)d_in[25]; const float* wbb = (const float*)d_in[26];
        gemm128_kernel<0, 0><<<g64, 256>>>(A, qw, qbb, Qb, 128);
        gemm128_kernel<0, 1><<<g64, 256>>>(A, kw, kbb, Kb, 128);
        gemm128_kernel<0, 0><<<g64, 256>>>(A, vw, vbb, Vb, 128);
        gemm128_kernel<0, 0><<<g64, 256>>>(A, ww, wbb, Rb, 128);
        flash_kernel<<<NTOK / 64, 256, FLASH_SMEM>>>(Qb, Kb, Vb, Rb, B, 0);
    }

    // fc1 (gelu) + fc2
    gemm128_kernel<1, 0><<<dim3(NTOK / 64, 2), 256>>>(B, fc1w, fc1b, H, 256);
    fc2_kernel<<<NTOK * 32 / 256, 256>>>(H, fc2w, fc2b, (float*)d_out);
}

// round 3
// speedup vs baseline: 5.1978x; 5.1978x over previous
#include <cuda_runtime.h>
#include <cuda_bf16.h>
#include <math.h>
#include <cstdint>

#define NTOK 8192
typedef unsigned long long u64;
typedef __nv_bfloat16 bf16;

// ---------------- scratch ----------------
__device__ float g_A[NTOK * 128];
__device__ float g_B[NTOK * 128];
__device__ float g_Qb[NTOK * 128];
__device__ float g_Kb[NTOK * 128];
__device__ float g_Vb[NTOK * 128];
__device__ float g_Rb[NTOK * 128];
__device__ float g_H[NTOK * 256];      // reused as O partials (2 x 1M floats)
__device__ float g_L[2 * NTOK];

// ---------------- helpers ----------------
__device__ __forceinline__ u64 dup2(float x) {
    u64 r; asm("mov.b64 %0, {%1, %1};" : "=l"(r) : "f"(x)); return r;
}
__device__ __forceinline__ void fma2(u64 &d, u64 a, u64 b) {
    asm("fma.rn.f32x2 %0, %1, %2, %0;" : "+l"(d) : "l"(a), "l"(b));
}
__device__ __forceinline__ float2 unp2(u64 v) {
    float2 f; asm("mov.b64 {%0, %1}, %2;" : "=f"(f.x), "=f"(f.y) : "l"(v)); return f;
}
__device__ __forceinline__ float gelu_f(float x) {
    return 0.5f * x * (1.0f + erff(x * 0.7071067811865476f));
}
__device__ __forceinline__ uint32_t pack_bf16(float lo, float hi) {
    uint32_t r; asm("cvt.rn.bf16x2.f32 %0, %1, %2;" : "=r"(r) : "f"(hi), "f"(lo)); return r;
}
__device__ __forceinline__ uint32_t smem_u32(const void* p) {
    uint32_t a; asm("{ .reg .u64 t; cvta.to.shared.u64 t, %1; cvt.u32.u64 %0, t; }" : "=r"(a) : "l"(p));
    return a;
}

// ---------------- mma.sync / ldmatrix / cp.async primitives ----------------
__device__ __forceinline__ void mma16816(float* c, const uint32_t* a, uint32_t b0, uint32_t b1) {
    asm volatile("mma.sync.aligned.m16n8k16.row.col.f32.bf16.bf16.f32 "
        "{%0,%1,%2,%3}, {%4,%5,%6,%7}, {%8,%9}, {%0,%1,%2,%3};"
        : "+f"(c[0]), "+f"(c[1]), "+f"(c[2]), "+f"(c[3])
        : "r"(a[0]), "r"(a[1]), "r"(a[2]), "r"(a[3]), "r"(b0), "r"(b1));
}
__device__ __forceinline__ void ldsm4(uint32_t* r, uint32_t addr) {
    asm volatile("ldmatrix.sync.aligned.m8n8.x4.shared.b16 {%0,%1,%2,%3}, [%4];"
        : "=r"(r[0]), "=r"(r[1]), "=r"(r[2]), "=r"(r[3]) : "r"(addr));
}
__device__ __forceinline__ void cp16(uint32_t sdst, const void* gsrc) {
    asm volatile("cp.async.cg.shared.global [%0], [%1], 16;" :: "r"(sdst), "l"(gsrc));
}
#define CP_COMMIT() asm volatile("cp.async.commit_group;" ::: "memory")
#define CP_WAIT1()  asm volatile("cp.async.wait_group 1;" ::: "memory")

// tile: 128 rows x 128 bf16, SMEM rows padded to 272 bytes (conflict-free ldmatrix)
#define TROW 272
#define TILE_BYTES (128 * TROW)

__device__ __forceinline__ void copy_tile_async(char* dst, const bf16* __restrict__ src,
                                                int rstride, int tid) {
    uint32_t d = smem_u32(dst);
#pragma unroll
    for (int rep = 0; rep < 8; rep++) {
        int chunk = rep * 256 + tid;       // 2048 chunks of 16B
        int r = chunk >> 4, c = chunk & 15;
        cp16(d + r * TROW + c * 16, src + (size_t)r * rstride + c * 8);
    }
}

// ---------------- fc0 ----------------
__global__ void __launch_bounds__(256) fc0_kernel(
    const float* __restrict__ x, const float* __restrict__ w,
    const float* __restrict__ b, float* __restrict__ out)
{
    int idx = blockIdx.x * 256 + threadIdx.x;
    int n = idx >> 7, c = idx & 127;
    float x0 = x[n * 3 + 0], x1 = x[n * 3 + 1], x2 = x[n * 3 + 2];
    out[idx] = fmaf(x0, w[c], fmaf(x1, w[128 + c], fmaf(x2, w[256 + c], b[c])));
}

// ---------------- generic GEMM, OUT: 0=f32, 1=f32+gelu, 2=bf16, 3=bf16 transposed ----------------
template<int OUT>
__global__ void __launch_bounds__(256) gemm128_kernel(
    const float* __restrict__ X, const float* __restrict__ W,
    const float* __restrict__ bias, float* __restrict__ C, int M)
{
    __shared__ float Xt[32][64];
    __shared__ float Ws[32][128];
    int tid = threadIdx.x;
    int n0 = blockIdx.x * 64;
    int cb = blockIdx.y * 128;
    int rg = tid >> 4, cg = tid & 15;

    u64 acc[4][4];
#pragma unroll
    for (int r = 0; r < 4; r++)
#pragma unroll
        for (int j = 0; j < 4; j++) acc[r][j] = 0ULL;

    for (int kc = 0; kc < 128; kc += 32) {
        __syncthreads();
        {
            int m = tid & 63, kk = (tid >> 6) << 2;
#pragma unroll
            for (int rep = 0; rep < 2; rep++) {
                float4 v = *(const float4*)&X[(n0 + m) * 128 + kc + kk];
                Xt[kk + 0][m] = v.x; Xt[kk + 1][m] = v.y;
                Xt[kk + 2][m] = v.z; Xt[kk + 3][m] = v.w;
                kk += 16;
            }
        }
        {
            int c4 = (tid & 31) << 2, k = tid >> 5;
#pragma unroll
            for (int rep = 0; rep < 4; rep++) {
                *(float4*)&Ws[k][c4] = *(const float4*)&W[(kc + k) * M + cb + c4];
                k += 8;
            }
        }
        __syncthreads();
#pragma unroll 8
        for (int k = 0; k < 32; k++) {
            float4 xv = *(const float4*)&Xt[k][rg << 2];
            const float* wrow = &Ws[k][cg << 3];
            ulonglong2 w0 = *(const ulonglong2*)(wrow);
            ulonglong2 w1 = *(const ulonglong2*)(wrow + 4);
            u64 x0 = dup2(xv.x), x1 = dup2(xv.y), x2 = dup2(xv.z), x3 = dup2(xv.w);
            fma2(acc[0][0], x0, w0.x); fma2(acc[0][1], x0, w0.y);
            fma2(acc[0][2], x0, w1.x); fma2(acc[0][3], x0, w1.y);
            fma2(acc[1][0], x1, w0.x); fma2(acc[1][1], x1, w0.y);
            fma2(acc[1][2], x1, w1.x); fma2(acc[1][3], x1, w1.y);
            fma2(acc[2][0], x2, w0.x); fma2(acc[2][1], x2, w0.y);
            fma2(acc[2][2], x2, w1.x); fma2(acc[2][3], x2, w1.y);
            fma2(acc[3][0], x3, w0.x); fma2(acc[3][1], x3, w0.y);
            fma2(acc[3][2], x3, w1.x); fma2(acc[3][3], x3, w1.y);
        }
    }

    float o[4][8];
#pragma unroll
    for (int r = 0; r < 4; r++)
#pragma unroll
        for (int j = 0; j < 4; j++) {
            float2 f = unp2(acc[r][j]);
            o[r][2 * j] = f.x; o[r][2 * j + 1] = f.y;
        }
#pragma unroll
    for (int r = 0; r < 4; r++)
#pragma unroll
        for (int j = 0; j < 8; j++) {
            float v = o[r][j] + bias[cb + (cg << 3) + j];
            if (OUT == 1) v = gelu_f(v);
            o[r][j] = v;
        }
    if (OUT == 0 || OUT == 1) {
#pragma unroll
        for (int r = 0; r < 4; r++) {
            int row = n0 + (rg << 2) + r;
            *(float4*)&C[row * M + cb + (cg << 3)]     = make_float4(o[r][0], o[r][1], o[r][2], o[r][3]);
            *(float4*)&C[row * M + cb + (cg << 3) + 4] = make_float4(o[r][4], o[r][5], o[r][6], o[r][7]);
        }
    } else if (OUT == 2) {
        bf16* Cb = (bf16*)C;
#pragma unroll
        for (int r = 0; r < 4; r++) {
            int row = n0 + (rg << 2) + r;
            uint32_t u0 = pack_bf16(o[r][0], o[r][1]);
            uint32_t u1 = pack_bf16(o[r][2], o[r][3]);
            uint32_t u2 = pack_bf16(o[r][4], o[r][5]);
            uint32_t u3 = pack_bf16(o[r][6], o[r][7]);
            *(int4*)&Cb[row * M + cb + (cg << 3)] = make_int4(u0, u1, u2, u3);
        }
    } else {   // bf16 transposed [c][NTOK]
        bf16* Cb = (bf16*)C;
#pragma unroll
        for (int j = 0; j < 8; j++) {
            int c = cb + (cg << 3) + j;
            uint32_t u0 = pack_bf16(o[0][j], o[1][j]);
            uint32_t u1 = pack_bf16(o[2][j], o[3][j]);
            *(uint2*)&Cb[(size_t)c * NTOK + n0 + (rg << 2)] = make_uint2(u0, u1);
        }
    }
}

// ---------------- flash attention via mma.sync (split-2, exp without max-sub) ----------------
// grid = 128: qblock = bx>>1, part = bx&1. Each CTA: 128 Q rows x 4096 keys, 8 warps x 16 rows.
// Q: [N,128] bf16, K: [N,128] bf16, Vt: [128][NTOK] bf16 (channel-major).
#define FK_SMEM (5 * TILE_BYTES)

__global__ void __launch_bounds__(256) flash_mma_kernel(
    const bf16* __restrict__ Q, const bf16* __restrict__ K,
    const bf16* __restrict__ Vt, float* __restrict__ Opart, float* __restrict__ Lpart)
{
    extern __shared__ char sm[];
    char* sQ = sm;
    char* sK[2] = { sm + TILE_BYTES, sm + 2 * TILE_BYTES };
    char* sV[2] = { sm + 3 * TILE_BYTES, sm + 4 * TILE_BYTES };

    int tid = threadIdx.x, wid = tid >> 5, lane = tid & 31;
    int qb = blockIdx.x >> 1, part = blockIdx.x & 1;
    int key0 = part * 4096;
    const float SCALE = 0.08838834764831843f;   // 1/sqrt(128)

    // prologue copies: group0 = Q,K0,V0 ; group1 = K1,V1
    copy_tile_async(sQ,    Q  + (size_t)(qb * 128) * 128, 128, tid);
    copy_tile_async(sK[0], K  + (size_t)key0 * 128,       128, tid);
    copy_tile_async(sV[0], Vt + key0,                    NTOK, tid);
    CP_COMMIT();
    copy_tile_async(sK[1], K  + (size_t)(key0 + 128) * 128, 128, tid);
    copy_tile_async(sV[1], Vt + key0 + 128,                NTOK, tid);
    CP_COMMIT();

    CP_WAIT1();          // group0 done
    __syncthreads();

    // Q fragments: 8 k-blocks x 4 regs, resident all loop
    uint32_t qf[8][4];
    {
        uint32_t qbase = smem_u32(sQ) + (wid * 16 + (lane & 15)) * TROW + (lane >> 4) * 16;
#pragma unroll
        for (int kb = 0; kb < 8; kb++) ldsm4(qf[kb], qbase + kb * 32);
    }

    float oacc[16][4];
#pragma unroll
    for (int nb = 0; nb < 16; nb++)
#pragma unroll
        for (int j = 0; j < 4; j++) oacc[nb][j] = 0.f;
    float lacc0 = 0.f, lacc1 = 0.f;

    uint32_t tb_off = (lane & 7) * TROW + (lane >> 3) * 16;   // ldmatrix per-thread base (K/V tiles)

    for (int i = 0; i < 32; i++) {
        int b = i & 1;
        CP_WAIT1();
        __syncthreads();          // tile i resident in buffer b

        uint32_t kB = smem_u32(sK[b]);
        uint32_t vB = smem_u32(sV[b]);
        uint32_t pf[8][4];

        // ---- S = Q K^T (per nb-pair), exp, pack to P fragments ----
#pragma unroll
        for (int j = 0; j < 8; j++) {
            float s0[4] = {0.f, 0.f, 0.f, 0.f};
            float s1[4] = {0.f, 0.f, 0.f, 0.f};
            uint32_t kf[16];
            uint32_t a0 = kB + (2 * j) * (8 * TROW) + tb_off;
#pragma unroll
            for (int q = 0; q < 4; q++) ldsm4(kf + 4 * q, a0 + q * 64);
#pragma unroll
            for (int s = 0; s < 8; s++) mma16816(s0, qf[s], kf[2 * s], kf[2 * s + 1]);
            uint32_t a1 = kB + (2 * j + 1) * (8 * TROW) + tb_off;
#pragma unroll
            for (int q = 0; q < 4; q++) ldsm4(kf + 4 * q, a1 + q * 64);
#pragma unroll
            for (int s = 0; s < 8; s++) mma16816(s1, qf[s], kf[2 * s], kf[2 * s + 1]);

            float e00 = __expf(s0[0] * SCALE), e01 = __expf(s0[1] * SCALE);
            float e02 = __expf(s0[2] * SCALE), e03 = __expf(s0[3] * SCALE);
            float e10 = __expf(s1[0] * SCALE), e11 = __expf(s1[1] * SCALE);
            float e12 = __expf(s1[2] * SCALE), e13 = __expf(s1[3] * SCALE);
            lacc0 += (e00 + e01) + (e10 + e11);
            lacc1 += (e02 + e03) + (e12 + e13);
            pf[j][0] = pack_bf16(e00, e01);
            pf[j][1] = pack_bf16(e02, e03);
            pf[j][2] = pack_bf16(e10, e11);
            pf[j][3] = pack_bf16(e12, e13);
        }

        // ---- O += P V ----
#pragma unroll
        for (int nb = 0; nb < 16; nb++) {
            uint32_t vf[16];
            uint32_t a = vB + nb * (8 * TROW) + tb_off;
#pragma unroll
            for (int q = 0; q < 4; q++) ldsm4(vf + 4 * q, a + q * 64);
#pragma unroll
            for (int s = 0; s < 8; s++) mma16816(oacc[nb], pf[s], vf[2 * s], vf[2 * s + 1]);
        }

        __syncthreads();          // everyone done reading buffer b
        if (i + 2 < 32) {
            copy_tile_async(sK[b], K  + (size_t)(key0 + (i + 2) * 128) * 128, 128, tid);
            copy_tile_async(sV[b], Vt + key0 + (i + 2) * 128,               NTOK, tid);
        }
        CP_COMMIT();              // keep group count uniform
    }

    // ---- epilogue: raw partial O + row sums ----
    int g = lane >> 2, tig = lane & 3;
    int row0 = qb * 128 + wid * 16 + g;
    float* o0 = Opart + ((size_t)part * NTOK + row0) * 128;
    float* o1 = o0 + 8 * 128;
#pragma unroll
    for (int nb = 0; nb < 16; nb++) {
        *(float2*)&o0[nb * 8 + tig * 2] = make_float2(oacc[nb][0], oacc[nb][1]);
        *(float2*)&o1[nb * 8 + tig * 2] = make_float2(oacc[nb][2], oacc[nb][3]);
    }
    lacc0 += __shfl_xor_sync(0xffffffffu, lacc0, 1);
    lacc0 += __shfl_xor_sync(0xffffffffu, lacc0, 2);
    lacc1 += __shfl_xor_sync(0xffffffffu, lacc1, 1);
    lacc1 += __shfl_xor_sync(0xffffffffu, lacc1, 2);
    if (tig == 0) {
        Lpart[part * NTOK + row0]     = lacc0;
        Lpart[part * NTOK + row0 + 8] = lacc1;
    }
}

// ---------------- combine split-2 partials + residual (+gelu) ----------------
__global__ void __launch_bounds__(256) combine_kernel(
    const float* __restrict__ Op, const float* __restrict__ Lp,
    const float* __restrict__ R, float* __restrict__ Out, int applyGelu)
{
    int idx = blockIdx.x * 256 + threadIdx.x;
    int row = idx >> 7;
    float l = Lp[row] + Lp[NTOK + row];
    float o = (Op[idx] + Op[(size_t)NTOK * 128 + idx]) * (1.0f / (l * 8192.0f));
    float v = o + R[idx];
    Out[idx] = applyGelu ? gelu_f(v) : v;
}

// ---------------- local attention ----------------
__global__ void __launch_bounds__(256) local_attn_kernel(
    const float* __restrict__ Q, const float* __restrict__ K,
    const float* __restrict__ V, const int* __restrict__ nbr,
    const float* __restrict__ R, float* __restrict__ Out)
{
    __shared__ float qs[8][128];
    __shared__ float ps[8][8][32];
    __shared__ int   js[8][32];
    int w = threadIdx.x >> 5, lane = threadIdx.x & 31;
    int n = blockIdx.x * 8 + w;

    float4 qv = *(const float4*)&Q[n * 128 + lane * 4];
    *(float4*)&qs[w][lane * 4] = make_float4(qv.x * 0.25f, qv.y * 0.25f, qv.z * 0.25f, qv.w * 0.25f);
    int j = nbr[n * 32 + lane];
    js[w][lane] = j;
    __syncwarp();

    const float* krow = K + j * 128;
    float sc[8];
#pragma unroll
    for (int h = 0; h < 8; h++) {
        float4 a0 = *(const float4*)&krow[h * 16 + 0];
        float4 a1 = *(const float4*)&krow[h * 16 + 4];
        float4 a2 = *(const float4*)&krow[h * 16 + 8];
        float4 a3 = *(const float4*)&krow[h * 16 + 12];
        const float* q = &qs[w][h * 16];
        sc[h] = q[0]*a0.x + q[1]*a0.y + q[2]*a0.z + q[3]*a0.w
              + q[4]*a1.x + q[5]*a1.y + q[6]*a1.z + q[7]*a1.w
              + q[8]*a2.x + q[9]*a2.y + q[10]*a2.z + q[11]*a2.w
              + q[12]*a3.x + q[13]*a3.y + q[14]*a3.z + q[15]*a3.w;
    }
#pragma unroll
    for (int h = 0; h < 8; h++) {
        float mx = sc[h];
#pragma unroll
        for (int o = 16; o; o >>= 1) mx = fmaxf(mx, __shfl_xor_sync(0xffffffffu, mx, o));
        float p = __expf(sc[h] - mx);
        float su = p;
#pragma unroll
        for (int o = 16; o; o >>= 1) su += __shfl_xor_sync(0xffffffffu, su, o);
        ps[w][h][lane] = p / su;
    }
    __syncwarp();

    float acc[4] = {0.f, 0.f, 0.f, 0.f};
#pragma unroll 4
    for (int k = 0; k < 32; k++) {
        int jj = js[w][k];
        const float* vrow = V + jj * 128;
#pragma unroll
        for (int i = 0; i < 4; i++) {
            int c = lane + 32 * i;
            acc[i] += ps[w][c >> 4][k] * vrow[c];
        }
    }
#pragma unroll
    for (int i = 0; i < 4; i++) {
        int c = lane + 32 * i;
        Out[n * 128 + c] = gelu_f(acc[i] + R[n * 128 + c]);
    }
}

// ---------------- fc2 ----------------
__global__ void __launch_bounds__(256) fc2_kernel(
    const float* __restrict__ H, const float* __restrict__ w,
    const float* __restrict__ b, float* __restrict__ out)
{
    int n = (blockIdx.x * 256 + threadIdx.x) >> 5;
    int lane = threadIdx.x & 31;
    const float4* h4 = (const float4*)(H + n * 256);
    const float4* w4 = (const float4*)w;
    float acc = 0.f;
#pragma unroll
    for (int i = 0; i < 2; i++) {
        float4 hv = h4[lane + 32 * i];
        float4 wv = w4[lane + 32 * i];
        acc += hv.x * wv.x + hv.y * wv.y + hv.z * wv.z + hv.w * wv.w;
    }
#pragma unroll
    for (int o = 16; o; o >>= 1) acc += __shfl_xor_sync(0xffffffffu, acc, o);
    if (!lane) out[n] = acc + b[0];
}

// ---------------- host orchestration ----------------
extern "C" void kernel_launch(void* const* d_in, const int* in_sizes, int n_in,
                              void* d_out, int out_size)
{
    (void)in_sizes; (void)n_in; (void)out_size;
    const float* x    = (const float*)d_in[0];
    const float* fc0w = (const float*)d_in[1];
    const float* fc0b = (const float*)d_in[2];
    const float* fc1w = (const float*)d_in[27];
    const float* fc1b = (const float*)d_in[28];
    const float* fc2w = (const float*)d_in[29];
    const float* fc2b = (const float*)d_in[30];
    const int*   nbr  = (const int*)d_in[31];

    float *A, *B, *Qb, *Kb, *Vb, *Rb, *H, *L;
    cudaGetSymbolAddress((void**)&A,  g_A);
    cudaGetSymbolAddress((void**)&B,  g_B);
    cudaGetSymbolAddress((void**)&Qb, g_Qb);
    cudaGetSymbolAddress((void**)&Kb, g_Kb);
    cudaGetSymbolAddress((void**)&Vb, g_Vb);
    cudaGetSymbolAddress((void**)&Rb, g_Rb);
    cudaGetSymbolAddress((void**)&H,  g_H);
    cudaGetSymbolAddress((void**)&L,  g_L);

    cudaFuncSetAttribute(flash_mma_kernel, cudaFuncAttributeMaxDynamicSharedMemorySize, FK_SMEM);

    dim3 g64(NTOK / 64, 1);

    fc0_kernel<<<NTOK * 128 / 256, 256>>>(x, fc0w, fc0b, A);

    // ---- layer 0 (global, gelu) ----
    {
        const float* qw = (const float*)d_in[3];  const float* qbb = (const float*)d_in[4];
        const float* kw = (const float*)d_in[5];  const float* kbb = (const float*)d_in[6];
        const float* vw = (const float*)d_in[7];  const float* vbb = (const float*)d_in[8];
        const float* ww = (const float*)d_in[9];  const float* wbb = (const float*)d_in[10];
        gemm128_kernel<2><<<g64, 256>>>(A, qw, qbb, Qb, 128);
        gemm128_kernel<2><<<g64, 256>>>(A, kw, kbb, Kb, 128);
        gemm128_kernel<3><<<g64, 256>>>(A, vw, vbb, Vb, 128);   // V transposed bf16 (channel-major)
        gemm128_kernel<0><<<g64, 256>>>(A, ww, wbb, Rb, 128);
        flash_mma_kernel<<<128, 256, FK_SMEM>>>((const bf16*)Qb, (const bf16*)Kb, (const bf16*)Vb, H, L);
        combine_kernel<<<NTOK * 128 / 256, 256>>>(H, L, Rb, B, 1);
    }

    // ---- layer 1 (local, gelu) ----
    {
        const float* qw = (const float*)d_in[11]; const float* qbb = (const float*)d_in[12];
        const float* kw = (const float*)d_in[13]; const float* kbb = (const float*)d_in[14];
        const float* vw = (const float*)d_in[15]; const float* vbb = (const float*)d_in[16];
        const float* ww = (const float*)d_in[17]; const float* wbb = (const float*)d_in[18];
        gemm128_kernel<0><<<g64, 256>>>(B, qw, qbb, Qb, 128);
        gemm128_kernel<0><<<g64, 256>>>(B, kw, kbb, Kb, 128);
        gemm128_kernel<0><<<g64, 256>>>(B, vw, vbb, Vb, 128);
        gemm128_kernel<0><<<g64, 256>>>(B, ww, wbb, Rb, 128);
        local_attn_kernel<<<NTOK / 8, 256>>>(Qb, Kb, Vb, nbr, Rb, A);
    }

    // ---- layer 2 (global, no activation) ----
    {
        const float* qw = (const float*)d_in[19]; const float* qbb = (const float*)d_in[20];
        const float* kw = (const float*)d_in[21]; const float* kbb = (const float*)d_in[22];
        const float* vw = (const float*)d_in[23]; const float* vbb = (const float*)d_in[24];
        const float* ww = (const float*)d_in[25]; const float* wbb = (const float*)d_in[26];
        gemm128_kernel<2><<<g64, 256>>>(A, qw, qbb, Qb, 128);
        gemm128_kernel<2><<<g64, 256>>>(A, kw, kbb, Kb, 128);
        gemm128_kernel<3><<<g64, 256>>>(A, vw, vbb, Vb, 128);
        gemm128_kernel<0><<<g64, 256>>>(A, ww, wbb, Rb, 128);
        flash_mma_kernel<<<128, 256, FK_SMEM>>>((const bf16*)Qb, (const bf16*)Kb, (const bf16*)Vb, H, L);
        combine_kernel<<<NTOK * 128 / 256, 256>>>(H, L, Rb, B, 0);
    }

    // fc1 (gelu) + fc2
    gemm128_kernel<1><<<dim3(NTOK / 64, 2), 256>>>(B, fc1w, fc1b, H, 256);
    fc2_kernel<<<NTOK * 32 / 256, 256>>>(H, fc2w, fc2b, (float*)d_out);
}

// round 4
// speedup vs baseline: 6.7953x; 1.3073x over previous
#include <cuda_runtime.h>
#include <cuda_bf16.h>
#include <math.h>
#include <cstdint>

#define NTOK 8192
typedef unsigned long long u64;
typedef __nv_bfloat16 bf16;

// ---------------- scratch ----------------
__device__ float g_Qb[NTOK * 128];
__device__ float g_Kb[NTOK * 128];
__device__ float g_Vb[NTOK * 128];
__device__ float g_Rb[NTOK * 128];
__device__ float g_H[NTOK * 256];      // reused as O partials (2 x 1M floats)
__device__ float g_L[2 * NTOK];
__device__ bf16  g_Xh[NTOK * 128];
__device__ bf16  g_Xl[NTOK * 128];
__device__ bf16  g_Wth[13 * 256 * 128];   // transposed bf16 weights [col][k]
__device__ bf16  g_Wtl[13 * 256 * 128];   // lo parts

// ---------------- helpers ----------------
__device__ __forceinline__ float gelu_f(float x) {
    return 0.5f * x * (1.0f + erff(x * 0.7071067811865476f));
}
__device__ __forceinline__ uint32_t pack_bf16(float lo, float hi) {
    uint32_t r; asm("cvt.rn.bf16x2.f32 %0, %1, %2;" : "=r"(r) : "f"(hi), "f"(lo)); return r;
}
__device__ __forceinline__ uint32_t smem_u32(const void* p) {
    uint32_t a; asm("{ .reg .u64 t; cvta.to.shared.u64 t, %1; cvt.u32.u64 %0, t; }" : "=r"(a) : "l"(p));
    return a;
}
__device__ __forceinline__ void split_bf16(float v, bf16& h, bf16& l) {
    h = __float2bfloat16(v);
    l = __float2bfloat16(v - __bfloat162float(h));
}

// ---------------- mma.sync / ldmatrix / cp.async primitives ----------------
__device__ __forceinline__ void mma16816(float* c, const uint32_t* a, uint32_t b0, uint32_t b1) {
    asm volatile("mma.sync.aligned.m16n8k16.row.col.f32.bf16.bf16.f32 "
        "{%0,%1,%2,%3}, {%4,%5,%6,%7}, {%8,%9}, {%0,%1,%2,%3};"
        : "+f"(c[0]), "+f"(c[1]), "+f"(c[2]), "+f"(c[3])
        : "r"(a[0]), "r"(a[1]), "r"(a[2]), "r"(a[3]), "r"(b0), "r"(b1));
}
__device__ __forceinline__ void ldsm4(uint32_t* r, uint32_t addr) {
    asm volatile("ldmatrix.sync.aligned.m8n8.x4.shared.b16 {%0,%1,%2,%3}, [%4];"
        : "=r"(r[0]), "=r"(r[1]), "=r"(r[2]), "=r"(r[3]) : "r"(addr));
}
__device__ __forceinline__ void cp16(uint32_t sdst, const void* gsrc) {
    asm volatile("cp.async.cg.shared.global [%0], [%1], 16;" :: "r"(sdst), "l"(gsrc));
}
#define CP_COMMIT() asm volatile("cp.async.commit_group;" ::: "memory")
#define CP_WAIT1()  asm volatile("cp.async.wait_group 1;" ::: "memory")
#define CP_WAIT0()  asm volatile("cp.async.wait_group 0;" ::: "memory")

// tile geometry: rows x 128 bf16, SMEM rows padded to 272 bytes
#define TROW 272
#define TILE_BYTES (128 * TROW)

__device__ __forceinline__ void copy_tile_async(char* dst, const bf16* __restrict__ src,
                                                int rstride, int tid) {
    uint32_t d = smem_u32(dst);
#pragma unroll
    for (int rep = 0; rep < 8; rep++) {
        int chunk = rep * 256 + tid;       // 2048 chunks of 16B (128 rows)
        int r = chunk >> 4, c = chunk & 15;
        cp16(d + r * TROW + c * 16, src + (size_t)r * rstride + c * 8);
    }
}
__device__ __forceinline__ void copy_x64_async(char* dst, const bf16* __restrict__ src, int tid) {
    uint32_t d = smem_u32(dst);
#pragma unroll
    for (int rep = 0; rep < 4; rep++) {
        int chunk = rep * 256 + tid;       // 1024 chunks (64 rows)
        int r = chunk >> 4, c = chunk & 15;
        cp16(d + r * TROW + c * 16, src + (size_t)r * 128 + c * 8);
    }
}

// ---------------- weight transpose + bf16 split (runs once per launch) ----------------
struct WPtrs { const float* w[13]; int cols[13]; };

__global__ void __launch_bounds__(256) wconv_kernel(WPtrs p, bf16* Wth, bf16* Wtl) {
    int m = blockIdx.z;
    int colsM = p.cols[m];
    int c0 = blockIdx.x * 32, k0 = blockIdx.y * 32;
    if (c0 >= colsM) return;
    __shared__ float t[32][33];
    int tx = threadIdx.x & 31, ty = threadIdx.x >> 5;   // 32 x 8
    const float* W = p.w[m];
#pragma unroll
    for (int i = 0; i < 4; i++) {
        int k = k0 + ty + 8 * i;
        t[ty + 8 * i][tx] = W[(size_t)k * colsM + c0 + tx];
    }
    __syncthreads();
    size_t slot = (size_t)m * 256 * 128;
#pragma unroll
    for (int i = 0; i < 4; i++) {
        int col = c0 + ty + 8 * i;
        int kk = k0 + tx;
        float v = t[tx][ty + 8 * i];
        bf16 h, l; split_bf16(v, h, l);
        Wth[slot + (size_t)col * 128 + kk] = h;
        Wtl[slot + (size_t)col * 128 + kk] = l;
    }
}

// ---------------- fc0: [N,3] @ [3,128] + b -> split bf16 ----------------
__global__ void __launch_bounds__(256) fc0_kernel(
    const float* __restrict__ x, const float* __restrict__ w,
    const float* __restrict__ b, bf16* __restrict__ Xh, bf16* __restrict__ Xl)
{
    int idx = blockIdx.x * 256 + threadIdx.x;
    int n = idx >> 7, c = idx & 127;
    float x0 = x[n * 3 + 0], x1 = x[n * 3 + 1], x2 = x[n * 3 + 2];
    float v = fmaf(x0, w[c], fmaf(x1, w[128 + c], fmaf(x2, w[256 + c], b[c])));
    bf16 h, l; split_bf16(v, h, l);
    Xh[idx] = h; Xl[idx] = l;
}

// ---------------- tensor-core GEMM: C = act(X[N,128] @ W[128,Mcols]) ----------------
// TERMS: 1 = Xh@Wh (bf16); 3 = Xh@Wh + Xl@Wh + Xh@Wl (~fp32 precision)
// OUT: 0=f32, 1=f32+gelu, 2=bf16, 3=bf16 transposed [col][NTOK]
#define GEMM_SMEM_1 (64 * TROW + 128 * TROW)
#define GEMM_SMEM_3 (2 * (64 * TROW + 128 * TROW))

template<int TERMS, int OUT>
__global__ void __launch_bounds__(256) mma_gemm_kernel(
    const bf16* __restrict__ Xh, const bf16* __restrict__ Xl,
    const bf16* __restrict__ Wth, const bf16* __restrict__ Wtl,
    const float* __restrict__ bias, float* __restrict__ C, int M)
{
    extern __shared__ char sm[];
    char* sXh = sm;
    char* sWh = sm + 64 * TROW;
    char* sXl = sWh + 128 * TROW;
    char* sWl = sXl + 64 * TROW;

    int tid = threadIdx.x, wid = tid >> 5, lane = tid & 31;
    int row0 = blockIdx.x * 64;
    int cb = blockIdx.y * 128;

    copy_x64_async(sXh, Xh + (size_t)row0 * 128, tid);
    copy_tile_async(sWh, Wth + (size_t)cb * 128, 128, tid);
    if (TERMS == 3) {
        copy_x64_async(sXl, Xl + (size_t)row0 * 128, tid);
        copy_tile_async(sWl, Wtl + (size_t)cb * 128, 128, tid);
    }
    CP_COMMIT();
    CP_WAIT0();
    __syncthreads();

    int rowBlk = wid & 3, colHalf = wid >> 2;
    uint32_t ah[8][4], al[8][4];
    {
        uint32_t qb_ = smem_u32(sXh) + (rowBlk * 16 + (lane & 15)) * TROW + (lane >> 4) * 16;
#pragma unroll
        for (int kb = 0; kb < 8; kb++) ldsm4(ah[kb], qb_ + kb * 32);
        if (TERMS == 3) {
            uint32_t ql_ = smem_u32(sXl) + (rowBlk * 16 + (lane & 15)) * TROW + (lane >> 4) * 16;
#pragma unroll
            for (int kb = 0; kb < 8; kb++) ldsm4(al[kb], ql_ + kb * 32);
        }
    }

    float acc[8][4];
#pragma unroll
    for (int nb = 0; nb < 8; nb++)
#pragma unroll
        for (int j = 0; j < 4; j++) acc[nb][j] = 0.f;

    uint32_t tb_off = (lane & 7) * TROW + (lane >> 3) * 16;
    uint32_t whB = smem_u32(sWh), wlB = smem_u32(sWl);

#pragma unroll
    for (int nb = 0; nb < 8; nb++) {
        uint32_t kf[16];
        uint32_t a = whB + (colHalf * 8 + nb) * (8 * TROW) + tb_off;
#pragma unroll
        for (int q = 0; q < 4; q++) ldsm4(kf + 4 * q, a + q * 64);
#pragma unroll
        for (int s = 0; s < 8; s++) mma16816(acc[nb], ah[s], kf[2 * s], kf[2 * s + 1]);
        if (TERMS == 3) {
#pragma unroll
            for (int s = 0; s < 8; s++) mma16816(acc[nb], al[s], kf[2 * s], kf[2 * s + 1]);
            uint32_t kl[16];
            uint32_t al_ = wlB + (colHalf * 8 + nb) * (8 * TROW) + tb_off;
#pragma unroll
            for (int q = 0; q < 4; q++) ldsm4(kl + 4 * q, al_ + q * 64);
#pragma unroll
            for (int s = 0; s < 8; s++) mma16816(acc[nb], ah[s], kl[2 * s], kl[2 * s + 1]);
        }
    }

    // epilogue
    int g = lane >> 2, tig = lane & 3;
    int r0 = row0 + rowBlk * 16 + g, r1 = r0 + 8;
#pragma unroll
    for (int nb = 0; nb < 8; nb++) {
        int col = cb + colHalf * 64 + nb * 8 + tig * 2;
        float b0 = bias[col], b1 = bias[col + 1];
        float v00 = acc[nb][0] + b0, v01 = acc[nb][1] + b1;
        float v10 = acc[nb][2] + b0, v11 = acc[nb][3] + b1;
        if (OUT == 1) { v00 = gelu_f(v00); v01 = gelu_f(v01); v10 = gelu_f(v10); v11 = gelu_f(v11); }
        if (OUT == 0 || OUT == 1) {
            *(float2*)&C[(size_t)r0 * M + col] = make_float2(v00, v01);
            *(float2*)&C[(size_t)r1 * M + col] = make_float2(v10, v11);
        } else if (OUT == 2) {
            bf16* Cb = (bf16*)C;
            *(uint32_t*)&Cb[(size_t)r0 * M + col] = pack_bf16(v00, v01);
            *(uint32_t*)&Cb[(size_t)r1 * M + col] = pack_bf16(v10, v11);
        } else {
            bf16* Cb = (bf16*)C;
            Cb[(size_t)col * NTOK + r0]       = __float2bfloat16(v00);
            Cb[(size_t)(col + 1) * NTOK + r0] = __float2bfloat16(v01);
            Cb[(size_t)col * NTOK + r1]       = __float2bfloat16(v10);
            Cb[(size_t)(col + 1) * NTOK + r1] = __float2bfloat16(v11);
        }
    }
}

// ---------------- flash attention via mma.sync (split-2, exp without max-sub) ----------------
#define FK_SMEM (5 * TILE_BYTES)

__global__ void __launch_bounds__(256) flash_mma_kernel(
    const bf16* __restrict__ Q, const bf16* __restrict__ K,
    const bf16* __restrict__ Vt, float* __restrict__ Opart, float* __restrict__ Lpart)
{
    extern __shared__ char sm[];
    char* sQ = sm;
    char* sK[2] = { sm + TILE_BYTES, sm + 2 * TILE_BYTES };
    char* sV[2] = { sm + 3 * TILE_BYTES, sm + 4 * TILE_BYTES };

    int tid = threadIdx.x, wid = tid >> 5, lane = tid & 31;
    int qb = blockIdx.x >> 1, part = blockIdx.x & 1;
    int key0 = part * 4096;
    const float SCALE = 0.08838834764831843f;   // 1/sqrt(128)

    copy_tile_async(sQ,    Q  + (size_t)(qb * 128) * 128, 128, tid);
    copy_tile_async(sK[0], K  + (size_t)key0 * 128,       128, tid);
    copy_tile_async(sV[0], Vt + key0,                    NTOK, tid);
    CP_COMMIT();
    copy_tile_async(sK[1], K  + (size_t)(key0 + 128) * 128, 128, tid);
    copy_tile_async(sV[1], Vt + key0 + 128,                NTOK, tid);
    CP_COMMIT();

    CP_WAIT1();
    __syncthreads();

    uint32_t qf[8][4];
    {
        uint32_t qbase = smem_u32(sQ) + (wid * 16 + (lane & 15)) * TROW + (lane >> 4) * 16;
#pragma unroll
        for (int kb = 0; kb < 8; kb++) ldsm4(qf[kb], qbase + kb * 32);
    }

    float oacc[16][4];
#pragma unroll
    for (int nb = 0; nb < 16; nb++)
#pragma unroll
        for (int j = 0; j < 4; j++) oacc[nb][j] = 0.f;
    float lacc0 = 0.f, lacc1 = 0.f;

    uint32_t tb_off = (lane & 7) * TROW + (lane >> 3) * 16;

    for (int i = 0; i < 32; i++) {
        int b = i & 1;
        CP_WAIT1();
        __syncthreads();

        uint32_t kB = smem_u32(sK[b]);
        uint32_t vB = smem_u32(sV[b]);
        uint32_t pf[8][4];

#pragma unroll
        for (int j = 0; j < 8; j++) {
            float s0[4] = {0.f, 0.f, 0.f, 0.f};
            float s1[4] = {0.f, 0.f, 0.f, 0.f};
            uint32_t kf[16];
            uint32_t a0 = kB + (2 * j) * (8 * TROW) + tb_off;
#pragma unroll
            for (int q = 0; q < 4; q++) ldsm4(kf + 4 * q, a0 + q * 64);
#pragma unroll
            for (int s = 0; s < 8; s++) mma16816(s0, qf[s], kf[2 * s], kf[2 * s + 1]);
            uint32_t a1 = kB + (2 * j + 1) * (8 * TROW) + tb_off;
#pragma unroll
            for (int q = 0; q < 4; q++) ldsm4(kf + 4 * q, a1 + q * 64);
#pragma unroll
            for (int s = 0; s < 8; s++) mma16816(s1, qf[s], kf[2 * s], kf[2 * s + 1]);

            float e00 = __expf(s0[0] * SCALE), e01 = __expf(s0[1] * SCALE);
            float e02 = __expf(s0[2] * SCALE), e03 = __expf(s0[3] * SCALE);
            float e10 = __expf(s1[0] * SCALE), e11 = __expf(s1[1] * SCALE);
            float e12 = __expf(s1[2] * SCALE), e13 = __expf(s1[3] * SCALE);
            lacc0 += (e00 + e01) + (e10 + e11);
            lacc1 += (e02 + e03) + (e12 + e13);
            pf[j][0] = pack_bf16(e00, e01);
            pf[j][1] = pack_bf16(e02, e03);
            pf[j][2] = pack_bf16(e10, e11);
            pf[j][3] = pack_bf16(e12, e13);
        }

#pragma unroll
        for (int nb = 0; nb < 16; nb++) {
            uint32_t vf[16];
            uint32_t a = vB + nb * (8 * TROW) + tb_off;
#pragma unroll
            for (int q = 0; q < 4; q++) ldsm4(vf + 4 * q, a + q * 64);
#pragma unroll
            for (int s = 0; s < 8; s++) mma16816(oacc[nb], pf[s], vf[2 * s], vf[2 * s + 1]);
        }

        __syncthreads();
        if (i + 2 < 32) {
            copy_tile_async(sK[b], K  + (size_t)(key0 + (i + 2) * 128) * 128, 128, tid);
            copy_tile_async(sV[b], Vt + key0 + (i + 2) * 128,               NTOK, tid);
        }
        CP_COMMIT();
    }

    int g = lane >> 2, tig = lane & 3;
    int row0 = qb * 128 + wid * 16 + g;
    float* o0 = Opart + ((size_t)part * NTOK + row0) * 128;
    float* o1 = o0 + 8 * 128;
#pragma unroll
    for (int nb = 0; nb < 16; nb++) {
        *(float2*)&o0[nb * 8 + tig * 2] = make_float2(oacc[nb][0], oacc[nb][1]);
        *(float2*)&o1[nb * 8 + tig * 2] = make_float2(oacc[nb][2], oacc[nb][3]);
    }
    lacc0 += __shfl_xor_sync(0xffffffffu, lacc0, 1);
    lacc0 += __shfl_xor_sync(0xffffffffu, lacc0, 2);
    lacc1 += __shfl_xor_sync(0xffffffffu, lacc1, 1);
    lacc1 += __shfl_xor_sync(0xffffffffu, lacc1, 2);
    if (tig == 0) {
        Lpart[part * NTOK + row0]     = lacc0;
        Lpart[part * NTOK + row0 + 8] = lacc1;
    }
}

// ---------------- combine split-2 partials + residual (+gelu) -> split bf16 ----------------
__global__ void __launch_bounds__(256) combine_kernel(
    const float* __restrict__ Op, const float* __restrict__ Lp,
    const float* __restrict__ R, bf16* __restrict__ Xh, bf16* __restrict__ Xl, int applyGelu)
{
    int idx = blockIdx.x * 256 + threadIdx.x;
    int row = idx >> 7;
    float l = Lp[row] + Lp[NTOK + row];
    float o = (Op[idx] + Op[(size_t)NTOK * 128 + idx]) * (1.0f / (l * 8192.0f));
    float v = o + R[idx];
    if (applyGelu) v = gelu_f(v);
    bf16 h, lo; split_bf16(v, h, lo);
    Xh[idx] = h; Xl[idx] = lo;
}

// ---------------- local attention -> split bf16 ----------------
__global__ void __launch_bounds__(256) local_attn_kernel(
    const float* __restrict__ Q, const float* __restrict__ K,
    const float* __restrict__ V, const int* __restrict__ nbr,
    const float* __restrict__ R, bf16* __restrict__ Xh, bf16* __restrict__ Xl)
{
    __shared__ float qs[8][128];
    __shared__ float ps[8][8][32];
    __shared__ int   js[8][32];
    int w = threadIdx.x >> 5, lane = threadIdx.x & 31;
    int n = blockIdx.x * 8 + w;

    float4 qv = *(const float4*)&Q[n * 128 + lane * 4];
    *(float4*)&qs[w][lane * 4] = make_float4(qv.x * 0.25f, qv.y * 0.25f, qv.z * 0.25f, qv.w * 0.25f);
    int j = nbr[n * 32 + lane];
    js[w][lane] = j;
    __syncwarp();

    const float* krow = K + (size_t)j * 128;
    float sc[8];
#pragma unroll
    for (int h = 0; h < 8; h++) {
        float4 a0 = *(const float4*)&krow[h * 16 + 0];
        float4 a1 = *(const float4*)&krow[h * 16 + 4];
        float4 a2 = *(const float4*)&krow[h * 16 + 8];
        float4 a3 = *(const float4*)&krow[h * 16 + 12];
        const float* q = &qs[w][h * 16];
        sc[h] = q[0]*a0.x + q[1]*a0.y + q[2]*a0.z + q[3]*a0.w
              + q[4]*a1.x + q[5]*a1.y + q[6]*a1.z + q[7]*a1.w
              + q[8]*a2.x + q[9]*a2.y + q[10]*a2.z + q[11]*a2.w
              + q[12]*a3.x + q[13]*a3.y + q[14]*a3.z + q[15]*a3.w;
    }
#pragma unroll
    for (int h = 0; h < 8; h++) {
        float mx = sc[h];
#pragma unroll
        for (int o = 16; o; o >>= 1) mx = fmaxf(mx, __shfl_xor_sync(0xffffffffu, mx, o));
        float p = __expf(sc[h] - mx);
        float su = p;
#pragma unroll
        for (int o = 16; o; o >>= 1) su += __shfl_xor_sync(0xffffffffu, su, o);
        ps[w][h][lane] = p / su;
    }
    __syncwarp();

    float acc[4] = {0.f, 0.f, 0.f, 0.f};
#pragma unroll 4
    for (int k = 0; k < 32; k++) {
        int jj = js[w][k];
        const float* vrow = V + (size_t)jj * 128;
#pragma unroll
        for (int i = 0; i < 4; i++) {
            int c = lane + 32 * i;
            acc[i] += ps[w][c >> 4][k] * vrow[c];
        }
    }
#pragma unroll
    for (int i = 0; i < 4; i++) {
        int c = lane + 32 * i;
        float v = gelu_f(acc[i] + R[n * 128 + c]);
        bf16 h, lo; split_bf16(v, h, lo);
        Xh[n * 128 + c] = h; Xl[n * 128 + c] = lo;
    }
}

// ---------------- fc2 ----------------
__global__ void __launch_bounds__(256) fc2_kernel(
    const float* __restrict__ H, const float* __restrict__ w,
    const float* __restrict__ b, float* __restrict__ out)
{
    int n = (blockIdx.x * 256 + threadIdx.x) >> 5;
    int lane = threadIdx.x & 31;
    const float4* h4 = (const float4*)(H + (size_t)n * 256);
    const float4* w4 = (const float4*)w;
    float acc = 0.f;
#pragma unroll
    for (int i = 0; i < 2; i++) {
        float4 hv = h4[lane + 32 * i];
        float4 wv = w4[lane + 32 * i];
        acc += hv.x * wv.x + hv.y * wv.y + hv.z * wv.z + hv.w * wv.w;
    }
#pragma unroll
    for (int o = 16; o; o >>= 1) acc += __shfl_xor_sync(0xffffffffu, acc, o);
    if (!lane) out[n] = acc + b[0];
}

// ---------------- host orchestration ----------------
extern "C" void kernel_launch(void* const* d_in, const int* in_sizes, int n_in,
                              void* d_out, int out_size)
{
    (void)in_sizes; (void)n_in; (void)out_size;
    const float* x    = (const float*)d_in[0];
    const float* fc0w = (const float*)d_in[1];
    const float* fc0b = (const float*)d_in[2];
    const float* fc1b = (const float*)d_in[28];
    const float* fc2w = (const float*)d_in[29];
    const float* fc2b = (const float*)d_in[30];
    const int*   nbr  = (const int*)d_in[31];

    float *Qb, *Kb, *Vb, *Rb, *H, *L;
    bf16 *Xh, *Xl, *Wth, *Wtl;
    cudaGetSymbolAddress((void**)&Qb, g_Qb);
    cudaGetSymbolAddress((void**)&Kb, g_Kb);
    cudaGetSymbolAddress((void**)&Vb, g_Vb);
    cudaGetSymbolAddress((void**)&Rb, g_Rb);
    cudaGetSymbolAddress((void**)&H,  g_H);
    cudaGetSymbolAddress((void**)&L,  g_L);
    cudaGetSymbolAddress((void**)&Xh, g_Xh);
    cudaGetSymbolAddress((void**)&Xl, g_Xl);
    cudaGetSymbolAddress((void**)&Wth, g_Wth);
    cudaGetSymbolAddress((void**)&Wtl, g_Wtl);

    cudaFuncSetAttribute(flash_mma_kernel, cudaFuncAttributeMaxDynamicSharedMemorySize, FK_SMEM);
    cudaFuncSetAttribute(mma_gemm_kernel<1,0>, cudaFuncAttributeMaxDynamicSharedMemorySize, GEMM_SMEM_1);
    cudaFuncSetAttribute(mma_gemm_kernel<1,2>, cudaFuncAttributeMaxDynamicSharedMemorySize, GEMM_SMEM_1);
    cudaFuncSetAttribute(mma_gemm_kernel<1,3>, cudaFuncAttributeMaxDynamicSharedMemorySize, GEMM_SMEM_1);
    cudaFuncSetAttribute(mma_gemm_kernel<3,0>, cudaFuncAttributeMaxDynamicSharedMemorySize, GEMM_SMEM_3);
    cudaFuncSetAttribute(mma_gemm_kernel<3,1>, cudaFuncAttributeMaxDynamicSharedMemorySize, GEMM_SMEM_3);

    // weight prep (once per call)
    {
        WPtrs p;
        for (int i = 0; i < 3; i++) {
            p.w[4 * i + 0] = (const float*)d_in[3 + 8 * i];       // q
            p.w[4 * i + 1] = (const float*)d_in[5 + 8 * i];       // k
            p.w[4 * i + 2] = (const float*)d_in[7 + 8 * i];       // v
            p.w[4 * i + 3] = (const float*)d_in[9 + 8 * i];       // w (residual)
            p.cols[4 * i + 0] = p.cols[4 * i + 1] = p.cols[4 * i + 2] = p.cols[4 * i + 3] = 128;
        }
        p.w[12] = (const float*)d_in[27];                          // fc1
        p.cols[12] = 256;
        wconv_kernel<<<dim3(8, 4, 13), 256>>>(p, Wth, Wtl);
    }
    const size_t SLOT = 256 * 128;

    fc0_kernel<<<NTOK * 128 / 256, 256>>>(x, fc0w, fc0b, Xh, Xl);

    dim3 g128(NTOK / 64, 1);

    // ---- layer 0 (global, gelu) ----
    {
        const float* qbb = (const float*)d_in[4];
        const float* kbb = (const float*)d_in[6];
        const float* vbb = (const float*)d_in[8];
        const float* wbb = (const float*)d_in[10];
        mma_gemm_kernel<1,2><<<g128, 256, GEMM_SMEM_1>>>(Xh, Xl, Wth + 0*SLOT, Wtl + 0*SLOT, qbb, Qb, 128);
        mma_gemm_kernel<1,2><<<g128, 256, GEMM_SMEM_1>>>(Xh, Xl, Wth + 1*SLOT, Wtl + 1*SLOT, kbb, Kb, 128);
        mma_gemm_kernel<1,3><<<g128, 256, GEMM_SMEM_1>>>(Xh, Xl, Wth + 2*SLOT, Wtl + 2*SLOT, vbb, Vb, 128);
        mma_gemm_kernel<3,0><<<g128, 256, GEMM_SMEM_3>>>(Xh, Xl, Wth + 3*SLOT, Wtl + 3*SLOT, wbb, Rb, 128);
        flash_mma_kernel<<<128, 256, FK_SMEM>>>((const bf16*)Qb, (const bf16*)Kb, (const bf16*)Vb, H, L);
        combine_kernel<<<NTOK * 128 / 256, 256>>>(H, L, Rb, Xh, Xl, 1);
    }

    // ---- layer 1 (local, gelu) ----
    {
        const float* qbb = (const float*)d_in[12];
        const float* kbb = (const float*)d_in[14];
        const float* vbb = (const float*)d_in[16];
        const float* wbb = (const float*)d_in[18];
        mma_gemm_kernel<1,0><<<g128, 256, GEMM_SMEM_1>>>(Xh, Xl, Wth + 4*SLOT, Wtl + 4*SLOT, qbb, Qb, 128);
        mma_gemm_kernel<1,0><<<g128, 256, GEMM_SMEM_1>>>(Xh, Xl, Wth + 5*SLOT, Wtl + 5*SLOT, kbb, Kb, 128);
        mma_gemm_kernel<1,0><<<g128, 256, GEMM_SMEM_1>>>(Xh, Xl, Wth + 6*SLOT, Wtl + 6*SLOT, vbb, Vb, 128);
        mma_gemm_kernel<3,0><<<g128, 256, GEMM_SMEM_3>>>(Xh, Xl, Wth + 7*SLOT, Wtl + 7*SLOT, wbb, Rb, 128);
        local_attn_kernel<<<NTOK / 8, 256>>>(Qb, Kb, Vb, nbr, Rb, Xh, Xl);
    }

    // ---- layer 2 (global, no activation) ----
    {
        const float* qbb = (const float*)d_in[20];
        const float* kbb = (const float*)d_in[22];
        const float* vbb = (const float*)d_in[24];
        const float* wbb = (const float*)d_in[26];
        mma_gemm_kernel<1,2><<<g128, 256, GEMM_SMEM_1>>>(Xh, Xl, Wth + 8*SLOT,  Wtl + 8*SLOT,  qbb, Qb, 128);
        mma_gemm_kernel<1,2><<<g128, 256, GEMM_SMEM_1>>>(Xh, Xl, Wth + 9*SLOT,  Wtl + 9*SLOT,  kbb, Kb, 128);
        mma_gemm_kernel<1,3><<<g128, 256, GEMM_SMEM_1>>>(Xh, Xl, Wth + 10*SLOT, Wtl + 10*SLOT, vbb, Vb, 128);
        mma_gemm_kernel<3,0><<<g128, 256, GEMM_SMEM_3>>>(Xh, Xl, Wth + 11*SLOT, Wtl + 11*SLOT, wbb, Rb, 128);
        flash_mma_kernel<<<128, 256, FK_SMEM>>>((const bf16*)Qb, (const bf16*)Kb, (const bf16*)Vb, H, L);
        combine_kernel<<<NTOK * 128 / 256, 256>>>(H, L, Rb, Xh, Xl, 0);
    }

    // fc1 (3-term, gelu) + fc2
    mma_gemm_kernel<3,1><<<dim3(NTOK / 64, 2), 256, GEMM_SMEM_3>>>(Xh, Xl, Wth + 12*SLOT, Wtl + 12*SLOT, fc1b, H, 256);
    fc2_kernel<<<NTOK * 32 / 256, 256>>>(H, fc2w, fc2b, (float*)d_out);
}